// round 9
// baseline (speedup 1.0000x reference)
#include <cuda_runtime.h>

#define NBINS 256
#define NREP  4
#define HIST_BLOCKS 1184
#define MAP_BLOCKS  1184

// ---------------- device globals (scratch; no allocation allowed) ----------
__device__ int   g_hist[6][NBINS];   // rows 0..2 = src ch0..2, rows 3..5 = tgt ch0..2
__device__ float g_dx[3][NBINS];     // cdf_src per channel
__device__ float g_dy[3][NBINS];     // pxmap per channel

// ---------------------------------------------------------------------------
__global__ void zero_hist_kernel() {
    int i = blockIdx.x * blockDim.x + threadIdx.x;
    if (i < 6 * NBINS) ((int*)g_hist)[i] = 0;
}

// exact match of ((img + 1.0f)*128.0f).astype(int32): two RN ops, trunc, clip
__device__ __forceinline__ int bin_of(float v) {
    float f = __fmul_rn(__fadd_rn(v, 1.0f), 128.0f);
    int b = (int)f;                                    // trunc toward zero
    return b < 0 ? 0 : (b > 255 ? 255 : b);
}

// ---------------------------------------------------------------------------
// Plain scalar histogram — structurally identical to the validated single-block
// recount, parallelized over blocks. No float4, no register aggregation, no
// tail special case. Replicas are pure address arithmetic.
__global__ void __launch_bounds__(256) hist_kernel(const float* __restrict__ src,
                                                   const float* __restrict__ tgt,
                                                   long nfloats) {
    __shared__ int sh[NREP][6][NBINS];
    int t = threadIdx.x;
    for (int i = t; i < NREP * 6 * NBINS; i += blockDim.x) ((int*)sh)[i] = 0;
    __syncthreads();

    int rep = (t >> 5) & (NREP - 1);
    long stride = (long)gridDim.x * blockDim.x;
    for (long e = (long)blockIdx.x * blockDim.x + t; e < nfloats; e += stride) {
        int c = (int)(e % 3);
        atomicAdd(&sh[rep][c][bin_of(src[e])], 1);
        atomicAdd(&sh[rep][3 + c][bin_of(tgt[e])], 1);
    }
    __syncthreads();

    for (int i = t; i < 6 * NBINS; i += blockDim.x) {
        int s = 0;
        #pragma unroll
        for (int r = 0; r < NREP; r++) s += ((int*)sh[r])[i];
        if (s) atomicAdd(&((int*)g_hist)[i], s);
    }
}

// ---------------------------------------------------------------------------
// jnp.searchsorted(a, x, side='left') over 256 entries
__device__ __forceinline__ int sst256(const float* a, float x) {
    int lo = 0, hi = NBINS;
    while (lo < hi) { int m = (lo + hi) >> 1; if (a[m] >= x) hi = m; else lo = m + 1; }
    return lo;
}

__global__ void build_kernel(int npix) {
    __shared__ float cs[3][NBINS], ct[3][NBINS];
    __shared__ int   cum[6][NBINS];
    int t = threadIdx.x;   // 256 threads

    if (t < 6) {
        int acc = 0;
        for (int k = 0; k < NBINS; k++) { acc += g_hist[t][k]; cum[t][k] = acc; }
    }
    __syncthreads();

    float denomN = (float)(npix - 1);
    #pragma unroll
    for (int c = 0; c < 3; c++) {
        // (cdf - cdf_min)*2/(npix-1) - 1 ; cdf_min = cdf[0]; all RN, no contraction
        float ds = (float)(cum[c][t]     - cum[c][0]);
        float dt = (float)(cum[3 + c][t] - cum[3 + c][0]);
        cs[c][t] = __fsub_rn(__fdiv_rn(__fmul_rn(ds, 2.0f), denomN), 1.0f);
        ct[c][t] = __fsub_rn(__fdiv_rn(__fmul_rn(dt, 2.0f), denomN), 1.0f);
    }
    __syncthreads();

    // pxmap = interpolate(dx=cdf_tgt (n=256), dy=grid (m=512), x=cdf_src)
    #pragma unroll
    for (int c = 0; c < 3; c++) {
        const float* dxa = ct[c];
        float x = cs[c][t];

        int j  = sst256(dxa, x);
        int c0 = j - 1; c0 = c0 < 0 ? 0 : (c0 > 255 ? 255 : c0);
        int c1 = j;     c1 = c1 < 0 ? 0 : (c1 > 255 ? 255 : c1);
        float da = fabsf(__fsub_rn(x, dxa[c0]));
        float db = fabsf(__fsub_rn(x, dxa[c1]));
        int nearr = (da <= db) ? c0 : c1;
        float v = dxa[nearr];
        int ind1 = nearr;
        while (ind1 > 0 && dxa[ind1 - 1] == v) --ind1;   // first occurrence
        int ind0 = ind1 - 1;
        int i0x = (ind0 < 0) ? ind0 + 256 : ind0;        // n = 256
        int i0y = (ind0 < 0) ? ind0 + 512 : ind0;        // m = 512
        float den = __fsub_rn(dxa[ind1], dxa[i0x]);
        float tt  = (den == 0.0f) ? 0.0f : __fdiv_rn(__fsub_rn(x, dxa[i0x]), den);
        float gy0 = __fsub_rn(__fdiv_rn((float)i0y,  256.0f), 1.0f);
        float gy1 = __fsub_rn(__fdiv_rn((float)ind1, 256.0f), 1.0f);
        float mid = __fmaf_rn(__fsub_rn(gy1, gy0), tt, gy0);
        float r = (x <= dxa[0]) ? -1.0f
                : ((x >= dxa[NBINS - 1]) ? 0.99609375f : mid);

        g_dx[c][t] = x;      // cdf_src
        g_dy[c][t] = r;      // pxmap
    }
}

// ---------------------------------------------------------------------------
// Literal transcription of interpolate(cdf_src, pxmap, x): n = m = 256.
__device__ __forceinline__ float mapv(const float* __restrict__ dxa,
                                      const float* __restrict__ dya,
                                      float x, float dx0, float dxl,
                                      float dy0, float dyl) {
    if (x <= dx0) return dy0;
    if (x >= dxl) return dyl;
    int lo = 0, hi = NBINS;
    while (lo < hi) { int m = (lo + hi) >> 1; if (dxa[m] >= x) hi = m; else lo = m + 1; }
    int j  = lo;
    int c0 = j - 1; c0 = c0 < 0 ? 0 : (c0 > 255 ? 255 : c0);
    int c1 = j;     c1 = c1 < 0 ? 0 : (c1 > 255 ? 255 : c1);
    float da = fabsf(__fsub_rn(x, dxa[c0]));
    float db = fabsf(__fsub_rn(x, dxa[c1]));
    int nearr = (da <= db) ? c0 : c1;
    float v = dxa[nearr];
    int ind1 = nearr;
    while (ind1 > 0 && dxa[ind1 - 1] == v) --ind1;
    int ind0 = ind1 - 1;
    int i0 = (ind0 < 0) ? ind0 + 256 : ind0;
    float d0  = dxa[i0];
    float den = __fsub_rn(v, d0);       // dx[ind1] == v
    float tt  = (den == 0.0f) ? 0.0f : __fdiv_rn(__fsub_rn(x, d0), den);
    float y0  = dya[i0], y1 = dya[ind1];
    return __fmaf_rn(__fsub_rn(y1, y0), tt, y0);
}

__global__ void __launch_bounds__(256) map_kernel(const float* __restrict__ src,
                                                  float* __restrict__ out,
                                                  long nfloats) {
    __shared__ float s_dx[3][NBINS];
    __shared__ float s_dy[3][NBINS];
    int t = threadIdx.x;
    for (int i = t; i < 3 * NBINS; i += blockDim.x) {
        ((float*)s_dx)[i] = ((const float*)g_dx)[i];
        ((float*)s_dy)[i] = ((const float*)g_dy)[i];
    }
    __syncthreads();

    float dx0[3], dxl[3], dy0[3], dyl[3];
    #pragma unroll
    for (int c = 0; c < 3; c++) {
        dx0[c] = s_dx[c][0]; dxl[c] = s_dx[c][NBINS - 1];
        dy0[c] = s_dy[c][0]; dyl[c] = s_dy[c][NBINS - 1];
    }

    long stride = (long)gridDim.x * blockDim.x;
    for (long e = (long)blockIdx.x * blockDim.x + t; e < nfloats; e += stride) {
        int c = (int)(e % 3);
        out[e] = mapv(s_dx[c], s_dy[c], src[e],
                      dx0[c], dxl[c], dy0[c], dyl[c]);
    }
}

// ---------------------------------------------------------------------------
extern "C" void kernel_launch(void* const* d_in, const int* in_sizes, int n_in,
                              void* d_out, int out_size) {
    const float* src = (const float*)d_in[0];
    const float* tgt = (const float*)d_in[1];
    float* out = (float*)d_out;
    long nfloats = (long)out_size;     // output has exactly src's shape
    int  npix    = (int)(nfloats / 3);

    zero_hist_kernel<<<6, 256>>>();
    hist_kernel<<<HIST_BLOCKS, 256>>>(src, tgt, nfloats);
    build_kernel<<<1, 256>>>(npix);
    map_kernel<<<MAP_BLOCKS, 256>>>(src, out, nfloats);
}

// round 10
// speedup vs baseline: 1.0431x; 1.0431x over previous
#include <cuda_runtime.h>

#define NBINS 256
#define LUTK  2048
#define NREP  4
#define HIST_BLOCKS 1184
#define MAP_BLOCKS  1184

// ---------------- device globals (scratch; no allocation allowed) ----------
__device__ int      g_hist[6][NBINS];   // rows 0..2 = src ch0..2, rows 3..5 = tgt ch0..2
__device__ float    g_dx[3][NBINS];     // cdf_src per channel
__device__ float    g_dy[3][NBINS];     // pxmap per channel
__device__ unsigned g_lut[3][LUTK];     // packed (jlo | jhi<<16) search windows

// ---------------------------------------------------------------------------
__global__ void zero_hist_kernel() {
    int i = blockIdx.x * blockDim.x + threadIdx.x;
    if (i < 6 * NBINS) ((int*)g_hist)[i] = 0;
}

// exact match of ((img + 1.0f)*128.0f).astype(int32): two RN ops, trunc, clip
__device__ __forceinline__ int bin_of(float v) {
    float f = __fmul_rn(__fadd_rn(v, 1.0f), 128.0f);
    int b = (int)f;                                    // trunc toward zero
    return b < 0 ? 0 : (b > 255 ? 255 : b);
}

// ---------------------------------------------------------------------------
// Plain scalar histogram (validated in R9 — do not touch this round).
__global__ void __launch_bounds__(256) hist_kernel(const float* __restrict__ src,
                                                   const float* __restrict__ tgt,
                                                   long nfloats) {
    __shared__ int sh[NREP][6][NBINS];
    int t = threadIdx.x;
    for (int i = t; i < NREP * 6 * NBINS; i += blockDim.x) ((int*)sh)[i] = 0;
    __syncthreads();

    int rep = (t >> 5) & (NREP - 1);
    long stride = (long)gridDim.x * blockDim.x;
    for (long e = (long)blockIdx.x * blockDim.x + t; e < nfloats; e += stride) {
        int c = (int)(e % 3);
        atomicAdd(&sh[rep][c][bin_of(src[e])], 1);
        atomicAdd(&sh[rep][3 + c][bin_of(tgt[e])], 1);
    }
    __syncthreads();

    for (int i = t; i < 6 * NBINS; i += blockDim.x) {
        int s = 0;
        #pragma unroll
        for (int r = 0; r < NREP; r++) s += ((int*)sh[r])[i];
        if (s) atomicAdd(&((int*)g_hist)[i], s);
    }
}

// ---------------------------------------------------------------------------
// jnp.searchsorted(a, x, side='left') over 256 entries
__device__ __forceinline__ int sst256(const float* a, float x) {
    int lo = 0, hi = NBINS;
    while (lo < hi) { int m = (lo + hi) >> 1; if (a[m] >= x) hi = m; else lo = m + 1; }
    return lo;
}

__global__ void build_kernel(int npix) {
    __shared__ float cs[3][NBINS], ct[3][NBINS];
    __shared__ int   cum[6][NBINS];
    int t = threadIdx.x;   // 256 threads

    if (t < 6) {
        int acc = 0;
        for (int k = 0; k < NBINS; k++) { acc += g_hist[t][k]; cum[t][k] = acc; }
    }
    __syncthreads();

    float denomN = (float)(npix - 1);
    #pragma unroll
    for (int c = 0; c < 3; c++) {
        float ds = (float)(cum[c][t]     - cum[c][0]);
        float dt = (float)(cum[3 + c][t] - cum[3 + c][0]);
        cs[c][t] = __fsub_rn(__fdiv_rn(__fmul_rn(ds, 2.0f), denomN), 1.0f);
        ct[c][t] = __fsub_rn(__fdiv_rn(__fmul_rn(dt, 2.0f), denomN), 1.0f);
    }
    __syncthreads();

    // pxmap = interpolate(dx=cdf_tgt (n=256), dy=grid (m=512), x=cdf_src)
    #pragma unroll
    for (int c = 0; c < 3; c++) {
        const float* dxa = ct[c];
        float x = cs[c][t];

        int j  = sst256(dxa, x);
        int c0 = j - 1; c0 = c0 < 0 ? 0 : (c0 > 255 ? 255 : c0);
        int c1 = j;     c1 = c1 < 0 ? 0 : (c1 > 255 ? 255 : c1);
        float da = fabsf(__fsub_rn(x, dxa[c0]));
        float db = fabsf(__fsub_rn(x, dxa[c1]));
        int nearr = (da <= db) ? c0 : c1;
        float v = dxa[nearr];
        int ind1 = nearr;
        while (ind1 > 0 && dxa[ind1 - 1] == v) --ind1;   // first occurrence
        int ind0 = ind1 - 1;
        int i0x = (ind0 < 0) ? ind0 + 256 : ind0;        // n = 256
        int i0y = (ind0 < 0) ? ind0 + 512 : ind0;        // m = 512
        float den = __fsub_rn(dxa[ind1], dxa[i0x]);
        float tt  = (den == 0.0f) ? 0.0f : __fdiv_rn(__fsub_rn(x, dxa[i0x]), den);
        float gy0 = __fsub_rn(__fdiv_rn((float)i0y,  256.0f), 1.0f);
        float gy1 = __fsub_rn(__fdiv_rn((float)ind1, 256.0f), 1.0f);
        float mid = __fmaf_rn(__fsub_rn(gy1, gy0), tt, gy0);
        float r = (x <= dxa[0]) ? -1.0f
                : ((x >= dxa[NBINS - 1]) ? 0.99609375f : mid);

        g_dx[c][t] = x;      // cdf_src
        g_dy[c][t] = r;      // pxmap
    }
    __syncthreads();

    // Search-window LUT over [-1,1): for x in bucket b, the true
    // j = searchsorted(cs, x) lies in [sst(lo)-1, sst(hi)+1] clamped to [1,255]
    // (interior x always has j in [1,255]; +-1 absorbs FP bucket-edge rounding).
    // Semantics-free: the windowed binary search returns the identical j.
    for (int i = t; i < 3 * LUTK; i += blockDim.x) {
        int c = i / LUTK, b = i % LUTK;
        float lo = (float)b       * (2.0f / LUTK) - 1.0f;
        float hi = (float)(b + 1) * (2.0f / LUTK) - 1.0f;
        int jlo = sst256(cs[c], lo) - 1;
        int jhi = sst256(cs[c], hi) + 1;
        jlo = jlo < 1   ? 1   : jlo;
        jhi = jhi > 255 ? 255 : jhi;
        if (jhi < jlo) jhi = jlo;
        g_lut[c][b] = (unsigned)jlo | ((unsigned)jhi << 16);
    }
}

// ---------------------------------------------------------------------------
// Literal transcription of interpolate(cdf_src, pxmap, x), with the
// searchsorted accelerated by a conservative LUT window (identical result).
__device__ __forceinline__ float mapv(const float* __restrict__ dxa,
                                      const float* __restrict__ dya,
                                      const unsigned* __restrict__ lut,
                                      float x, float dx0, float dxl,
                                      float dy0, float dyl) {
    if (x <= dx0) return dy0;
    if (x >= dxl) return dyl;
    // interior: x in (-1, 1) strictly, bucket index safe after clamp
    int b = (int)__fmul_rn(__fadd_rn(x, 1.0f), (float)(LUTK / 2));
    b = b < 0 ? 0 : (b > LUTK - 1 ? LUTK - 1 : b);
    unsigned w = lut[b];
    int lo = (int)(w & 0xffffu), hi = (int)(w >> 16);
    while (lo < hi) { int m = (lo + hi) >> 1; if (dxa[m] >= x) hi = m; else lo = m + 1; }
    int j  = lo;                          // == searchsorted(dxa, x), in [1,255]
    float a0 = dxa[j - 1], a1 = dxa[j];
    float da = fabsf(__fsub_rn(x, a0));
    float db = fabsf(__fsub_rn(x, a1));
    int nl = (da <= db);
    float v = nl ? a0 : a1;
    int ind1 = nl ? (j - 1) : j;
    while (ind1 > 0 && dxa[ind1 - 1] == v) --ind1;   // first occurrence
    int ind0 = ind1 - 1;
    int i0 = (ind0 < 0) ? ind0 + 256 : ind0;
    float d0  = dxa[i0];
    float den = __fsub_rn(dxa[ind1], d0);
    float tt  = (den == 0.0f) ? 0.0f : __fdiv_rn(__fsub_rn(x, d0), den);
    float y0  = dya[i0], y1 = dya[ind1];
    return __fmaf_rn(__fsub_rn(y1, y0), tt, y0);
}

__global__ void __launch_bounds__(256) map_kernel(const float* __restrict__ src,
                                                  float* __restrict__ out,
                                                  long nfloats) {
    __shared__ float    s_dx[3][NBINS];
    __shared__ float    s_dy[3][NBINS];
    __shared__ unsigned s_lut[3][LUTK];
    int t = threadIdx.x;
    for (int i = t; i < 3 * NBINS; i += blockDim.x) {
        ((float*)s_dx)[i] = ((const float*)g_dx)[i];
        ((float*)s_dy)[i] = ((const float*)g_dy)[i];
    }
    for (int i = t; i < 3 * LUTK; i += blockDim.x)
        ((unsigned*)s_lut)[i] = ((const unsigned*)g_lut)[i];
    __syncthreads();

    float dx0[3], dxl[3], dy0[3], dyl[3];
    #pragma unroll
    for (int c = 0; c < 3; c++) {
        dx0[c] = s_dx[c][0]; dxl[c] = s_dx[c][NBINS - 1];
        dy0[c] = s_dy[c][0]; dyl[c] = s_dy[c][NBINS - 1];
    }

    long stride = (long)gridDim.x * blockDim.x;
    for (long e = (long)blockIdx.x * blockDim.x + t; e < nfloats; e += stride) {
        int c = (int)(e % 3);
        out[e] = mapv(s_dx[c], s_dy[c], s_lut[c], src[e],
                      dx0[c], dxl[c], dy0[c], dyl[c]);
    }
}

// ---------------------------------------------------------------------------
extern "C" void kernel_launch(void* const* d_in, const int* in_sizes, int n_in,
                              void* d_out, int out_size) {
    const float* src = (const float*)d_in[0];
    const float* tgt = (const float*)d_in[1];
    float* out = (float*)d_out;
    long nfloats = (long)out_size;     // output has exactly src's shape
    int  npix    = (int)(nfloats / 3);

    zero_hist_kernel<<<6, 256>>>();
    hist_kernel<<<HIST_BLOCKS, 256>>>(src, tgt, nfloats);
    build_kernel<<<1, 256>>>(npix);
    map_kernel<<<MAP_BLOCKS, 256>>>(src, out, nfloats);
}

// round 11
// speedup vs baseline: 1.8215x; 1.7462x over previous
#include <cuda_runtime.h>

#define NBINS 256
#define LUTK  1024
#define NREP  4
#define HIST_BLOCKS 1184
#define MAP_BLOCKS  1184

// ---------------- device globals (scratch; no allocation allowed) ----------
__device__ int      g_hist[6][NBINS];   // rows 0..2 = src ch0..2, rows 3..5 = tgt ch0..2
__device__ float    g_dx[3][NBINS];     // cdf_src per channel
__device__ float    g_dy[3][NBINS];     // pxmap per channel
__device__ unsigned g_lut[3][LUTK];     // packed (jlo | jhi<<16) search windows

// ---------------------------------------------------------------------------
__global__ void zero_hist_kernel() {
    int i = blockIdx.x * blockDim.x + threadIdx.x;
    if (i < 6 * NBINS) ((int*)g_hist)[i] = 0;
}

// exact match of ((img + 1.0f)*128.0f).astype(int32): two RN ops, trunc, clip
__device__ __forceinline__ int bin_of(float v) {
    float f = __fmul_rn(__fadd_rn(v, 1.0f), 128.0f);
    int b = (int)f;                                    // trunc toward zero
    return b < 0 ? 0 : (b > 255 ? 255 : b);
}

// ---------------------------------------------------------------------------
// Plain scalar histogram (validated in R9 — untouched).
__global__ void __launch_bounds__(256) hist_kernel(const float* __restrict__ src,
                                                   const float* __restrict__ tgt,
                                                   long nfloats) {
    __shared__ int sh[NREP][6][NBINS];
    int t = threadIdx.x;
    for (int i = t; i < NREP * 6 * NBINS; i += blockDim.x) ((int*)sh)[i] = 0;
    __syncthreads();

    int rep = (t >> 5) & (NREP - 1);
    long stride = (long)gridDim.x * blockDim.x;
    for (long e = (long)blockIdx.x * blockDim.x + t; e < nfloats; e += stride) {
        int c = (int)(e % 3);
        atomicAdd(&sh[rep][c][bin_of(src[e])], 1);
        atomicAdd(&sh[rep][3 + c][bin_of(tgt[e])], 1);
    }
    __syncthreads();

    for (int i = t; i < 6 * NBINS; i += blockDim.x) {
        int s = 0;
        #pragma unroll
        for (int r = 0; r < NREP; r++) s += ((int*)sh[r])[i];
        if (s) atomicAdd(&((int*)g_hist)[i], s);
    }
}

// ---------------------------------------------------------------------------
__device__ __forceinline__ int sst256(const float* a, float x) {
    int lo = 0, hi = NBINS;
    while (lo < hi) { int m = (lo + hi) >> 1; if (a[m] >= x) hi = m; else lo = m + 1; }
    return lo;
}

__global__ void build_kernel(int npix) {
    __shared__ float cs[3][NBINS], ct[3][NBINS];
    __shared__ int   cum[6][NBINS];
    int t = threadIdx.x;   // 256 threads

    if (t < 6) {
        int acc = 0;
        for (int k = 0; k < NBINS; k++) { acc += g_hist[t][k]; cum[t][k] = acc; }
    }
    __syncthreads();

    float denomN = (float)(npix - 1);
    #pragma unroll
    for (int c = 0; c < 3; c++) {
        float ds = (float)(cum[c][t]     - cum[c][0]);
        float dt = (float)(cum[3 + c][t] - cum[3 + c][0]);
        cs[c][t] = __fsub_rn(__fdiv_rn(__fmul_rn(ds, 2.0f), denomN), 1.0f);
        ct[c][t] = __fsub_rn(__fdiv_rn(__fmul_rn(dt, 2.0f), denomN), 1.0f);
    }
    __syncthreads();

    // pxmap = interpolate(dx=cdf_tgt (n=256), dy=grid (m=512), x=cdf_src)
    #pragma unroll
    for (int c = 0; c < 3; c++) {
        const float* dxa = ct[c];
        float x = cs[c][t];

        int j  = sst256(dxa, x);
        int c0 = j - 1; c0 = c0 < 0 ? 0 : (c0 > 255 ? 255 : c0);
        int c1 = j;     c1 = c1 < 0 ? 0 : (c1 > 255 ? 255 : c1);
        float da = fabsf(__fsub_rn(x, dxa[c0]));
        float db = fabsf(__fsub_rn(x, dxa[c1]));
        int nearr = (da <= db) ? c0 : c1;
        float v = dxa[nearr];
        int ind1 = nearr;
        while (ind1 > 0 && dxa[ind1 - 1] == v) --ind1;   // first occurrence
        int ind0 = ind1 - 1;
        int i0x = (ind0 < 0) ? ind0 + 256 : ind0;        // n = 256
        int i0y = (ind0 < 0) ? ind0 + 512 : ind0;        // m = 512
        float den = __fsub_rn(dxa[ind1], dxa[i0x]);
        float tt  = (den == 0.0f) ? 0.0f : __fdiv_rn(__fsub_rn(x, dxa[i0x]), den);
        float gy0 = __fsub_rn(__fdiv_rn((float)i0y,  256.0f), 1.0f);
        float gy1 = __fsub_rn(__fdiv_rn((float)ind1, 256.0f), 1.0f);
        float mid = __fmaf_rn(__fsub_rn(gy1, gy0), tt, gy0);
        float r = (x <= dxa[0]) ? -1.0f
                : ((x >= dxa[NBINS - 1]) ? 0.99609375f : mid);

        g_dx[c][t] = x;      // cdf_src
        g_dy[c][t] = r;      // pxmap
    }
    __syncthreads();

    // Conservative search-window LUT over [-1,1): identical-result accelerator.
    for (int i = t; i < 3 * LUTK; i += blockDim.x) {
        int c = i / LUTK, b = i % LUTK;
        float lo = (float)b       * (2.0f / LUTK) - 1.0f;
        float hi = (float)(b + 1) * (2.0f / LUTK) - 1.0f;
        int jlo = sst256(cs[c], lo) - 1;
        int jhi = sst256(cs[c], hi) + 1;
        jlo = jlo < 1   ? 1   : jlo;
        jhi = jhi > 255 ? 255 : jhi;
        if (jhi < jlo) jhi = jlo;
        g_lut[c][b] = (unsigned)jlo | ((unsigned)jhi << 16);
    }
}

// ---------------------------------------------------------------------------
// Literal transcription of interpolate(cdf_src, pxmap, x), LUT-windowed search
// (identical result to full searchsorted).
__device__ __forceinline__ float mapv(const float* __restrict__ dxa,
                                      const float* __restrict__ dya,
                                      const unsigned* __restrict__ lut,
                                      float x, float dx0, float dxl,
                                      float dy0, float dyl) {
    if (x <= dx0) return dy0;
    if (x >= dxl) return dyl;
    int b = (int)__fmul_rn(__fadd_rn(x, 1.0f), (float)(LUTK / 2));
    b = b < 0 ? 0 : (b > LUTK - 1 ? LUTK - 1 : b);
    unsigned w = lut[b];
    int lo = (int)(w & 0xffffu), hi = (int)(w >> 16);
    while (lo < hi) { int m = (lo + hi) >> 1; if (dxa[m] >= x) hi = m; else lo = m + 1; }
    int j  = lo;                          // == searchsorted(dxa, x), in [1,255]
    float a0 = dxa[j - 1], a1 = dxa[j];
    float da = fabsf(__fsub_rn(x, a0));
    float db = fabsf(__fsub_rn(x, a1));
    int nl = (da <= db);
    float v = nl ? a0 : a1;
    int ind1 = nl ? (j - 1) : j;
    while (ind1 > 0 && dxa[ind1 - 1] == v) --ind1;   // first occurrence
    int ind0 = ind1 - 1;
    int i0 = (ind0 < 0) ? ind0 + 256 : ind0;
    float d0  = dxa[i0];
    float den = __fsub_rn(dxa[ind1], d0);
    float tt  = (den == 0.0f) ? 0.0f : __fdiv_rn(__fsub_rn(x, d0), den);
    float y0  = dya[i0], y1 = dya[ind1];
    return __fmaf_rn(__fsub_rn(y1, y0), tt, y0);
}

// float4 map: 4 independent mapv chains per thread for latency hiding.
// nfloats % 12 == 0 so quads are whole; channel of element 4i+k:
// (4i)%3 == i%3, then +1, +2, +0 (mod 3).
__global__ void __launch_bounds__(256) map_kernel(const float4* __restrict__ src4,
                                                  float4* __restrict__ out4,
                                                  long nquads) {
    __shared__ float    s_dx[3][NBINS];
    __shared__ float    s_dy[3][NBINS];
    __shared__ unsigned s_lut[3][LUTK];
    int t = threadIdx.x;
    for (int i = t; i < 3 * NBINS; i += blockDim.x) {
        ((float*)s_dx)[i] = ((const float*)g_dx)[i];
        ((float*)s_dy)[i] = ((const float*)g_dy)[i];
    }
    for (int i = t; i < 3 * LUTK; i += blockDim.x)
        ((unsigned*)s_lut)[i] = ((const unsigned*)g_lut)[i];
    __syncthreads();

    float dx0[3], dxl[3], dy0[3], dyl[3];
    #pragma unroll
    for (int c = 0; c < 3; c++) {
        dx0[c] = s_dx[c][0]; dxl[c] = s_dx[c][NBINS - 1];
        dy0[c] = s_dy[c][0]; dyl[c] = s_dy[c][NBINS - 1];
    }

    long stride = (long)gridDim.x * blockDim.x;
    for (long i = (long)blockIdx.x * blockDim.x + t; i < nquads; i += stride) {
        float4 v = src4[i];
        int cb = (int)(i % 3);             // channel of element 4i
        int c1 = cb + 1 == 3 ? 0 : cb + 1;
        int c2 = c1 + 1 == 3 ? 0 : c1 + 1;
        float4 r;
        r.x = mapv(s_dx[cb], s_dy[cb], s_lut[cb], v.x, dx0[cb], dxl[cb], dy0[cb], dyl[cb]);
        r.y = mapv(s_dx[c1], s_dy[c1], s_lut[c1], v.y, dx0[c1], dxl[c1], dy0[c1], dyl[c1]);
        r.z = mapv(s_dx[c2], s_dy[c2], s_lut[c2], v.z, dx0[c2], dxl[c2], dy0[c2], dyl[c2]);
        r.w = mapv(s_dx[cb], s_dy[cb], s_lut[cb], v.w, dx0[cb], dxl[cb], dy0[cb], dyl[cb]);
        out4[i] = r;
    }
}

// ---------------------------------------------------------------------------
extern "C" void kernel_launch(void* const* d_in, const int* in_sizes, int n_in,
                              void* d_out, int out_size) {
    const float* src = (const float*)d_in[0];
    const float* tgt = (const float*)d_in[1];
    float* out = (float*)d_out;
    long nfloats = (long)out_size;     // output has exactly src's shape
    long nquads  = nfloats / 4;        // nfloats % 12 == 0
    int  npix    = (int)(nfloats / 3);

    zero_hist_kernel<<<6, 256>>>();
    hist_kernel<<<HIST_BLOCKS, 256>>>(src, tgt, nfloats);
    build_kernel<<<1, 256>>>(npix);
    map_kernel<<<MAP_BLOCKS, 256>>>((const float4*)src, (float4*)out, nquads);
}